// round 7
// baseline (speedup 1.0000x reference)
#include <cuda_runtime.h>
#include <float.h>

#define NB 16384
#define NN 524288
#define NE 1048576
#define DEMB 128
#define DSTATE 64
#define NSTATES 10
#define MAXSTAGE 80

// Scratch (device globals — no allocation allowed)
__device__ float g_logits[NN];   // overflow fallback only
__device__ int   g_starts[NB + 1];

// ---------------- packed fp32x2 helpers ----------------
__device__ __forceinline__ unsigned long long pk2(float x, float y) {
    unsigned long long r;
    asm("mov.b64 %0, {%1, %2};" : "=l"(r) : "f"(x), "f"(y));
    return r;
}
__device__ __forceinline__ float2 upk2(unsigned long long v) {
    float2 r;
    asm("mov.b64 {%0, %1}, %2;" : "=f"(r.x), "=f"(r.y) : "l"(v));
    return r;
}
__device__ __forceinline__ unsigned long long ffma2(unsigned long long a,
                                                    unsigned long long b,
                                                    unsigned long long c) {
    unsigned long long d;
    asm("fma.rn.f32x2 %0, %1, %2, %3;" : "=l"(d) : "l"(a), "l"(b), "l"(c));
    return d;
}

// ---------------- K0: segment starts from sorted batch ----------------
__global__ void k_starts(const int* __restrict__ batch) {
    int n = blockIdx.x * blockDim.x + threadIdx.x;
    if (n >= NN) return;
    int bn = __ldg(&batch[n]);
    if (n == 0) {
        for (int b = 0; b <= bn; b++) g_starts[b] = 0;
    } else {
        int bp = __ldg(&batch[n - 1]);
        for (int b = bp + 1; b <= bn; b++) g_starts[b] = n;
    }
    if (n == NN - 1) {
        for (int b = bn + 1; b <= NB; b++) g_starts[b] = NN;
    }
}

// ---------------- K1a: copy edge_attr part (32 floats/edge) ----------------
__global__ __launch_bounds__(256) void k_edge_copy(
    const float4* __restrict__ ea4,   // [E*8]
    float4*       __restrict__ out4)  // rows of 24 float4
{
    unsigned idx = blockIdx.x * blockDim.x + threadIdx.x;
    if (idx >= NE * 8u) return;
    unsigned e = idx >> 3;
    unsigned c = idx & 7u;
    float4 v = __ldcs(&ea4[idx]);
    __stcs(&out4[e * 24u + c], v);
}

// ---------------- K1b: broadcast state_emb part (64 floats/edge) ----------------
__global__ __launch_bounds__(256) void k_edge_state(
    const int*    __restrict__ ei0,   // [E]
    const int*    __restrict__ batch, // [N]
    const int*    __restrict__ state, // [B]
    const float4* __restrict__ se4,   // [10*16]
    float4*       __restrict__ out4)
{
    unsigned idx = blockIdx.x * blockDim.x + threadIdx.x;
    if (idx >= NE * 16u) return;
    unsigned e = idx >> 4;
    unsigned c = idx & 15u;
    int src = __ldg(&ei0[e]);
    int b   = __ldg(&batch[src]);
    int s   = __ldg(&state[b]);
    float4 v = __ldg(&se4[(unsigned)s * 16u + c]);
    __stcs(&out4[e * 24u + 8u + c], v);
}

// ---------------- K2: fused logits + segment softmax + pool + concat ----------------
// Persistent block-per-graph. W1 atom-part lives in REGISTERS (packed u64 pairs).
// z_atom rows staged once in smem, reused for logits and pooling.
__global__ __launch_bounds__(256) void k_fused(
    const float4* __restrict__ z4,     // z_atom as float4 [N*32]
    const float*  __restrict__ z_mol,  // [B,128]
    const float*  __restrict__ semb,   // [10,64]
    const float*  __restrict__ W1,     // [192,32]
    const float*  __restrict__ b1,     // [32]
    const float*  __restrict__ W2,     // [32]
    const float*  __restrict__ b2,     // [1]
    const int*    __restrict__ state,  // [B]
    float*        __restrict__ out)    // x at out[0 .. B*256)
{
    __shared__ float zrow[MAXSTAGE * 128];   // 40 KB staging (also W1 bounce)
    __shared__ float sp_all[NSTATES * 32];
    __shared__ float lw[MAXSTAGE];
    __shared__ float red[8];
    __shared__ float pacc[256];

    int tid  = threadIdx.x;
    int lane = tid & 31;
    int wid  = tid >> 5;

    // ---- one-time per block: W1 atom part -> registers (via smem bounce) ----
    for (int t = tid; t < DEMB * 32; t += 256)
        zrow[t] = __ldg(&W1[t]);
    __syncthreads();

    unsigned long long w01[32], w23[32];
    #pragma unroll
    for (int kk2 = 0; kk2 < 32; kk2++) {
        w01[kk2] = pk2(zrow[(4 * kk2 + 0) * 32 + lane], zrow[(4 * kk2 + 1) * 32 + lane]);
        w23[kk2] = pk2(zrow[(4 * kk2 + 2) * 32 + lane], zrow[(4 * kk2 + 3) * 32 + lane]);
    }
    float w2v = __ldg(&W2[lane]);
    float b2v = __ldg(&b2[0]);
    __syncthreads();

    // ---- one-time: state-part contributions sp_all[s][j] = b1[j] + semb[s]@W1b[:,j] ----
    for (int t = tid; t < NSTATES * 32; t += 256) {
        int s = t >> 5, j = t & 31;
        float acc = __ldg(&b1[j]);
        #pragma unroll 8
        for (int m = 0; m < DSTATE; m++)
            acc += __ldg(&semb[s * DSTATE + m]) * __ldg(&W1[(DEMB + m) * 32 + j]);
        sp_all[t] = acc;
    }
    __syncthreads();

    // ---- persistent loop over graphs ----
    for (int b = blockIdx.x; b < NB; b += gridDim.x) {
        int lo  = g_starts[b];
        int hi  = g_starts[b + 1];
        int cnt = hi - lo;
        int sg  = __ldg(&state[b]);
        int stg = cnt < MAXSTAGE ? cnt : MAXSTAGE;

        __syncthreads();   // zrow/lw from previous graph fully consumed

        // stage z_atom rows (coalesced)
        for (int i = tid; i < stg * 32; i += 256)
            ((float4*)zrow)[i] = z4[(size_t)lo * 32 + i];
        __syncthreads();

        // ---- logits: warp per node, lane = hidden unit j ----
        float spv = sp_all[sg * 32 + lane];
        for (int i = wid; i < cnt; i += 8) {
            unsigned long long accA = pk2(spv, 0.f);
            unsigned long long accB = pk2(0.f, 0.f);
            if (i < stg) {
                const ulonglong2* ar = (const ulonglong2*)(zrow + i * 128);
                #pragma unroll
                for (int kk2 = 0; kk2 < 32; kk2++) {
                    ulonglong2 a = ar[kk2];   // LDS.128 broadcast (1 phase)
                    accA = ffma2(a.x, w01[kk2], accA);
                    accB = ffma2(a.y, w23[kk2], accB);
                }
            } else {   // overflow fallback (cnt > MAXSTAGE; statistically never)
                const ulonglong2* ar = (const ulonglong2*)(z4 + (size_t)(lo + i) * 32);
                #pragma unroll
                for (int kk2 = 0; kk2 < 32; kk2++) {
                    ulonglong2 a = ar[kk2];
                    accA = ffma2(a.x, w01[kk2], accA);
                    accB = ffma2(a.y, w23[kk2], accB);
                }
            }
            float2 uA = upk2(accA), uB = upk2(accB);
            float t = uA.x + uA.y + uB.x + uB.y;
            t = t > 0.f ? t : 0.01f * t;
            float c = t * w2v;
            #pragma unroll
            for (int off = 16; off; off >>= 1)
                c += __shfl_xor_sync(0xffffffffu, c, off);
            if (lane == 0) {
                float lg = c + b2v;
                if (i < MAXSTAGE) lw[i] = lg;
                else              g_logits[lo + i] = lg;
            }
        }
        __syncthreads();

        // ---- segment max ----
        float m = -FLT_MAX;
        for (int i = tid; i < cnt; i += 256) {
            float v = (i < MAXSTAGE) ? lw[i] : g_logits[lo + i];
            m = fmaxf(m, v);
        }
        #pragma unroll
        for (int off = 16; off; off >>= 1)
            m = fmaxf(m, __shfl_xor_sync(0xffffffffu, m, off));
        if (lane == 0) red[wid] = m;
        __syncthreads();
        m = red[0];
        #pragma unroll
        for (int r = 1; r < 8; r++) m = fmaxf(m, red[r]);
        __syncthreads();   // red about to be reused

        // ---- exp + segment sum (weights stored in place) ----
        float ssum = 0.f;
        for (int i = tid; i < cnt; i += 256) {
            float v = (i < MAXSTAGE) ? lw[i] : g_logits[lo + i];
            float e = __expf(v - m);
            if (i < MAXSTAGE) lw[i] = e;
            else              g_logits[lo + i] = e;
            ssum += e;
        }
        #pragma unroll
        for (int off = 16; off; off >>= 1)
            ssum += __shfl_xor_sync(0xffffffffu, ssum, off);
        if (lane == 0) red[wid] = ssum;
        __syncthreads();
        float s = red[0] + red[1] + red[2] + red[3] + red[4] + red[5] + red[6] + red[7];
        float inv = 1.f / (s + 1e-16f);

        // ---- weighted pool: 2 thread-groups of 128 dims, nodes split by parity ----
        int d    = tid & 127;
        int half = tid >> 7;
        float acc = 0.f;
        for (int i = half; i < cnt; i += 2) {
            float e  = (i < MAXSTAGE) ? lw[i] : g_logits[lo + i];
            float zv = (i < stg) ? zrow[i * 128 + d]
                                 : __ldg((const float*)z4 + (size_t)(lo + i) * 128 + d);
            acc += e * zv;
        }
        pacc[tid] = acc;
        __syncthreads();
        if (tid < 128) {
            float tot = (pacc[tid] + pacc[tid + 128]) * inv;
            out[(size_t)b * 256 + 128 + tid] = tot;
            out[(size_t)b * 256 + tid] = __ldg(&z_mol[(size_t)b * 128 + tid]);
        }
    }
}

// ---------------- launcher ----------------
extern "C" void kernel_launch(void* const* d_in, const int* in_sizes, int n_in,
                              void* d_out, int out_size) {
    const float* edge_attr = (const float*)d_in[0];
    const float* z_mol     = (const float*)d_in[1];
    const float* z_atom    = (const float*)d_in[2];
    const float* state_emb = (const float*)d_in[3];
    const float* W1        = (const float*)d_in[4];
    const float* b1        = (const float*)d_in[5];
    const float* W2        = (const float*)d_in[6];
    const float* b2        = (const float*)d_in[7];
    const int*   state     = (const int*)d_in[8];
    const int*   ei0       = (const int*)d_in[9];
    const int*   batch     = (const int*)d_in[10];
    float* out = (float*)d_out;

    (void)in_sizes; (void)n_in; (void)out_size;

    k_starts<<<(NN + 255) / 256, 256>>>(batch);

    k_fused<<<2048, 256>>>(
        (const float4*)z_atom, z_mol, state_emb, W1, b1, W2, b2, state, out);

    k_edge_copy<<<(NE * 8 + 255) / 256, 256>>>(
        (const float4*)edge_attr,
        (float4*)(out + (size_t)NB * 256));

    k_edge_state<<<(NE * 16 + 255) / 256, 256>>>(
        ei0, batch, state, (const float4*)state_emb,
        (float4*)(out + (size_t)NB * 256));
}

// round 10
// speedup vs baseline: 2.2013x; 2.2013x over previous
#include <cuda_runtime.h>
#include <float.h>

#define NB 16384
#define NN 524288
#define NE 1048576
#define DEMB 128
#define DSTATE 64
#define NSTATES 10

// Scratch (device globals — no allocation allowed)
__device__ float g_logits[NN];
__device__ int   g_starts[NB + 1];

// ---------------- packed fp32x2 helpers ----------------
__device__ __forceinline__ unsigned long long pk2(float x, float y) {
    unsigned long long r;
    asm("mov.b64 %0, {%1, %2};" : "=l"(r) : "f"(x), "f"(y));
    return r;
}
__device__ __forceinline__ float2 upk2(unsigned long long v) {
    float2 r;
    asm("mov.b64 {%0, %1}, %2;" : "=f"(r.x), "=f"(r.y) : "l"(v));
    return r;
}
__device__ __forceinline__ unsigned long long ffma2(unsigned long long a,
                                                    unsigned long long b,
                                                    unsigned long long c) {
    unsigned long long d;
    asm("fma.rn.f32x2 %0, %1, %2, %3;" : "=l"(d) : "l"(a), "l"(b), "l"(c));
    return d;
}

// ---------------- K0: segment starts from sorted batch ----------------
__global__ void k_starts(const int* __restrict__ batch) {
    int n = blockIdx.x * blockDim.x + threadIdx.x;
    if (n >= NN) return;
    int bn = __ldg(&batch[n]);
    if (n == 0) {
        for (int b = 0; b <= bn; b++) g_starts[b] = 0;
    } else {
        int bp = __ldg(&batch[n - 1]);
        for (int b = bp + 1; b <= bn; b++) g_starts[b] = n;
    }
    if (n == NN - 1) {
        for (int b = bn + 1; b <= NB; b++) g_starts[b] = NN;
    }
}

// ---------------- K1a: copy edge_attr part (32 floats/edge), 2 chunks/thread ----
__global__ __launch_bounds__(256) void k_edge_copy(
    const float4* __restrict__ ea4,   // [E*8]
    float4*       __restrict__ out4)  // rows of 24 float4
{
    unsigned idx = blockIdx.x * blockDim.x + threadIdx.x;   // 0 .. NE*4-1
    const unsigned stride = NE * 4u;
    unsigned i0 = idx, i1 = idx + stride;
    float4 v0 = __ldcs(&ea4[i0]);
    float4 v1 = __ldcs(&ea4[i1]);
    unsigned e0 = i0 >> 3, c0 = i0 & 7u;
    unsigned e1 = i1 >> 3, c1 = i1 & 7u;
    __stcs(&out4[e0 * 24u + c0], v0);
    __stcs(&out4[e1 * 24u + c1], v1);
}

// ---------------- K1b: state_emb broadcast (64 floats/edge), 4 chunks/thread ----
// Batches 4 independent ei0->batch->state chains to cover L2 latency (MLP=4).
__global__ __launch_bounds__(256) void k_edge_state(
    const int*    __restrict__ ei0,   // [E]
    const int*    __restrict__ batch, // [N]
    const int*    __restrict__ state, // [B]
    const float4* __restrict__ se4,   // [10*16]
    float4*       __restrict__ out4)
{
    unsigned idx0 = blockIdx.x * blockDim.x + threadIdx.x;  // 0 .. NE*4-1
    const unsigned stride = NE * 4u;

    unsigned e[4], c[4];
    int src[4], b[4], s[4];
    #pragma unroll
    for (int u = 0; u < 4; u++) {
        unsigned idx = idx0 + u * stride;
        e[u] = idx >> 4;
        c[u] = idx & 15u;
    }
    #pragma unroll
    for (int u = 0; u < 4; u++) src[u] = __ldg(&ei0[e[u]]);
    #pragma unroll
    for (int u = 0; u < 4; u++) b[u] = __ldg(&batch[src[u]]);
    #pragma unroll
    for (int u = 0; u < 4; u++) s[u] = __ldg(&state[b[u]]);
    #pragma unroll
    for (int u = 0; u < 4; u++) {
        float4 v = __ldg(&se4[(unsigned)s[u] * 16u + c[u]]);
        __stcs(&out4[e[u] * 24u + 8u + c[u]], v);
    }
}

// ---------------- K2: logits, lane-per-node, broadcast weights ----------------
// Each warp computes 32 nodes. Weights W1[:128] in smem, read as broadcast
// ulonglong2 (1 crossbar phase). z staged per-warp in 16-k chunks, transposed
// [k][node] layout (conflict-free). h[32] lives in 16 packed u64 accumulators.
#define KC 16
__global__ __launch_bounds__(256) void k_logits(
    const float4* __restrict__ z4,    // z_atom as float4 [N*32]
    const float*  __restrict__ semb,  // [10,64]
    const float*  __restrict__ W1,    // [192,32]
    const float*  __restrict__ b1,    // [32]
    const float*  __restrict__ W2,    // [32]
    const float*  __restrict__ b2,    // [1]
    const int*    __restrict__ state, // [B]
    const int*    __restrict__ batch) // [N]
{
    __shared__ float ws[DEMB * 32];          // 16 KB, [k][j] row-major (matches W1)
    __shared__ float zs[8 * KC * 33];        // per-warp staging, [k][node], 16.9 KB
    __shared__ float sp_t[32 * 11];          // state part, [j][s] transposed
    __shared__ float w2s[32];

    int tid  = threadIdx.x;
    int lane = tid & 31;
    int wid  = tid >> 5;

    for (int t = tid; t < DEMB * 32; t += 256)
        ws[t] = __ldg(&W1[t]);
    for (int t = tid; t < 32 * 11; t += 256) {
        int j = t / 11, s = t - j * 11;
        float acc = 0.f;
        if (s < NSTATES) {
            acc = __ldg(&b1[j]);
            #pragma unroll 8
            for (int m = 0; m < DSTATE; m++)
                acc += __ldg(&semb[s * DSTATE + m]) * __ldg(&W1[(DEMB + m) * 32 + j]);
        }
        sp_t[t] = acc;
    }
    if (tid < 32) w2s[tid] = __ldg(&W2[tid]);
    __syncthreads();
    float b2v = __ldg(&b2[0]);

    // exact cover: 2048 blocks * 8 warps * 32 nodes = NN
    unsigned n0 = (blockIdx.x * 8u + wid) * 32u;
    float* zsw = zs + wid * (KC * 33);

    int sidx = __ldg(&state[__ldg(&batch[n0 + lane])]);

    unsigned long long acc[16];
    #pragma unroll
    for (int q = 0; q < 16; q++) acc[q] = 0ull;

    int f  = lane & 3;
    int nd = lane >> 2;

    for (int cb = 0; cb < DEMB / 4 / 4; cb++) {   // 8 chunks of 16 k-values
        // stage: 4 lanes per node, 4 float4 = 16 k per node
        #pragma unroll
        for (int i = 0; i < 4; i++) {
            int node = nd + i * 8;
            float4 v = __ldg(&z4[(size_t)(n0 + node) * 32u + cb * 4 + f]);
            int kb = f * 4;
            zsw[(kb + 0) * 33 + node] = v.x;
            zsw[(kb + 1) * 33 + node] = v.y;
            zsw[(kb + 2) * 33 + node] = v.z;
            zsw[(kb + 3) * 33 + node] = v.w;
        }
        __syncwarp();

        #pragma unroll
        for (int k = 0; k < KC; k++) {
            float zv = zsw[k * 33 + lane];
            unsigned long long zvv = pk2(zv, zv);
            const ulonglong2* wr = (const ulonglong2*)(ws + (cb * KC + k) * 32);
            #pragma unroll
            for (int p = 0; p < 8; p++) {
                ulonglong2 wp = wr[p];      // broadcast LDS.128: 4 weights
                acc[2 * p]     = ffma2(zvv, wp.x, acc[2 * p]);
                acc[2 * p + 1] = ffma2(zvv, wp.y, acc[2 * p + 1]);
            }
        }
        __syncwarp();
    }

    // leaky-relu + W2 dot (acc[q] holds hidden units 2q, 2q+1)
    float c = 0.f;
    #pragma unroll
    for (int q = 0; q < 16; q++) {
        float2 h2 = upk2(acc[q]);
        int j0 = 2 * q, j1 = 2 * q + 1;
        float h0 = h2.x + sp_t[j0 * 11 + sidx];
        float h1 = h2.y + sp_t[j1 * 11 + sidx];
        h0 = h0 > 0.f ? h0 : 0.01f * h0;
        h1 = h1 > 0.f ? h1 : 0.01f * h1;
        c += h0 * w2s[j0] + h1 * w2s[j1];
    }
    g_logits[n0 + lane] = c + b2v;
}

// ---------------- K3: segment softmax + weighted pool + concat z_mol ----------
__global__ __launch_bounds__(128) void k_pool(
    const float* __restrict__ z_atom, // [N,128]
    const float* __restrict__ z_mol,  // [B,128]
    float*       __restrict__ out)    // x at out[0 .. B*256)
{
    int b = blockIdx.x;
    int tid = threadIdx.x;
    int lane = tid & 31, wid = tid >> 5;
    int lo = g_starts[b], hi = g_starts[b + 1];
    int cnt = hi - lo;

    __shared__ float se[1024];
    __shared__ float red[4];

    // segment max
    float m = -FLT_MAX;
    for (int i = tid; i < cnt; i += 128) m = fmaxf(m, g_logits[lo + i]);
    #pragma unroll
    for (int off = 16; off; off >>= 1) m = fmaxf(m, __shfl_xor_sync(0xffffffffu, m, off));
    if (lane == 0) red[wid] = m;
    __syncthreads();
    m = fmaxf(fmaxf(red[0], red[1]), fmaxf(red[2], red[3]));
    __syncthreads();

    // exp + segment sum (cache exp weights in smem)
    float s = 0.f;
    for (int i = tid; i < cnt; i += 128) {
        float e = __expf(g_logits[lo + i] - m);
        if (i < 1024) se[i] = e;
        s += e;
    }
    #pragma unroll
    for (int off = 16; off; off >>= 1) s += __shfl_xor_sync(0xffffffffu, s, off);
    if (lane == 0) red[wid] = s;
    __syncthreads();
    s = red[0] + red[1] + red[2] + red[3];
    float inv = 1.f / (s + 1e-16f);

    // weighted pool, 4 independent chains for MLP
    const float* za = z_atom + (size_t)lo * 128 + tid;
    float a0 = 0.f, a1 = 0.f, a2 = 0.f, a3 = 0.f;
    int i = 0;
    for (; i + 4 <= cnt; i += 4) {
        float e0 = (i + 0 < 1024) ? se[i + 0] : __expf(g_logits[lo + i + 0] - m);
        float e1 = (i + 1 < 1024) ? se[i + 1] : __expf(g_logits[lo + i + 1] - m);
        float e2 = (i + 2 < 1024) ? se[i + 2] : __expf(g_logits[lo + i + 2] - m);
        float e3 = (i + 3 < 1024) ? se[i + 3] : __expf(g_logits[lo + i + 3] - m);
        float z0 = za[(size_t)(i + 0) * 128];
        float z1 = za[(size_t)(i + 1) * 128];
        float z2 = za[(size_t)(i + 2) * 128];
        float z3 = za[(size_t)(i + 3) * 128];
        a0 += e0 * z0; a1 += e1 * z1; a2 += e2 * z2; a3 += e3 * z3;
    }
    for (; i < cnt; i++) {
        float e = (i < 1024) ? se[i] : __expf(g_logits[lo + i] - m);
        a0 += e * za[(size_t)i * 128];
    }
    float acc = (a0 + a1) + (a2 + a3);

    out[(size_t)b * 256 + tid]       = __ldg(&z_mol[(size_t)b * 128 + tid]);
    out[(size_t)b * 256 + 128 + tid] = acc * inv;
}

// ---------------- launcher ----------------
extern "C" void kernel_launch(void* const* d_in, const int* in_sizes, int n_in,
                              void* d_out, int out_size) {
    const float* edge_attr = (const float*)d_in[0];
    const float* z_mol     = (const float*)d_in[1];
    const float* z_atom    = (const float*)d_in[2];
    const float* state_emb = (const float*)d_in[3];
    const float* W1        = (const float*)d_in[4];
    const float* b1        = (const float*)d_in[5];
    const float* W2        = (const float*)d_in[6];
    const float* b2        = (const float*)d_in[7];
    const int*   state     = (const int*)d_in[8];
    const int*   ei0       = (const int*)d_in[9];
    const int*   batch     = (const int*)d_in[10];
    float* out = (float*)d_out;

    (void)in_sizes; (void)n_in; (void)out_size;

    k_starts<<<(NN + 255) / 256, 256>>>(batch);

    k_logits<<<NN / 256, 256>>>(   // 2048 blocks, exact cover
        (const float4*)z_atom, state_emb, W1, b1, W2, b2, state, batch);

    k_edge_copy<<<(NE * 4) / 256, 256>>>(
        (const float4*)edge_attr,
        (float4*)(out + (size_t)NB * 256));

    k_edge_state<<<(NE * 4) / 256, 256>>>(
        ei0, batch, state, (const float4*)state_emb,
        (float4*)(out + (size_t)NB * 256));

    k_pool<<<NB, 128>>>(z_atom, z_mol, out);
}

// round 11
// speedup vs baseline: 2.2678x; 1.0302x over previous
#include <cuda_runtime.h>
#include <float.h>

#define NB 16384
#define NN 524288
#define NE 1048576
#define DEMB 128
#define DSTATE 64
#define NSTATES 10

// Scratch (device globals — no allocation allowed)
__device__ float g_logits[NN];
__device__ int   g_starts[NB + 1];

// ---------------- packed fp32x2 helpers ----------------
__device__ __forceinline__ unsigned long long pk2(float x, float y) {
    unsigned long long r;
    asm("mov.b64 %0, {%1, %2};" : "=l"(r) : "f"(x), "f"(y));
    return r;
}
__device__ __forceinline__ float2 upk2(unsigned long long v) {
    float2 r;
    asm("mov.b64 {%0, %1}, %2;" : "=f"(r.x), "=f"(r.y) : "l"(v));
    return r;
}
__device__ __forceinline__ unsigned long long ffma2(unsigned long long a,
                                                    unsigned long long b,
                                                    unsigned long long c) {
    unsigned long long d;
    asm("fma.rn.f32x2 %0, %1, %2, %3;" : "=l"(d) : "l"(a), "l"(b), "l"(c));
    return d;
}

// ---------------- K0: segment starts from sorted batch ----------------
__global__ void k_starts(const int* __restrict__ batch) {
    int n = blockIdx.x * blockDim.x + threadIdx.x;
    if (n >= NN) return;
    int bn = __ldg(&batch[n]);
    if (n == 0) {
        for (int b = 0; b <= bn; b++) g_starts[b] = 0;
    } else {
        int bp = __ldg(&batch[n - 1]);
        for (int b = bp + 1; b <= bn; b++) g_starts[b] = n;
    }
    if (n == NN - 1) {
        for (int b = bn + 1; b <= NB; b++) g_starts[b] = NN;
    }
}

// ---------------- K1a: copy edge_attr part (32 floats/edge), 2 chunks/thread ----
__global__ __launch_bounds__(256) void k_edge_copy(
    const float4* __restrict__ ea4,   // [E*8]
    float4*       __restrict__ out4)  // rows of 24 float4
{
    unsigned idx = blockIdx.x * blockDim.x + threadIdx.x;   // 0 .. NE*4-1
    const unsigned stride = NE * 4u;
    unsigned i0 = idx, i1 = idx + stride;
    float4 v0 = __ldcs(&ea4[i0]);
    float4 v1 = __ldcs(&ea4[i1]);
    unsigned e0 = i0 >> 3, c0 = i0 & 7u;
    unsigned e1 = i1 >> 3, c1 = i1 & 7u;
    __stcs(&out4[e0 * 24u + c0], v0);
    __stcs(&out4[e1 * 24u + c1], v1);
}

// ---------------- K1b: state_emb broadcast (64 floats/edge), 4 chunks/thread ----
__global__ __launch_bounds__(256) void k_edge_state(
    const int*    __restrict__ ei0,   // [E]
    const int*    __restrict__ batch, // [N]
    const int*    __restrict__ state, // [B]
    const float4* __restrict__ se4,   // [10*16]
    float4*       __restrict__ out4)
{
    unsigned idx0 = blockIdx.x * blockDim.x + threadIdx.x;  // 0 .. NE*4-1
    const unsigned stride = NE * 4u;

    unsigned e[4], c[4];
    int src[4], b[4], s[4];
    #pragma unroll
    for (int u = 0; u < 4; u++) {
        unsigned idx = idx0 + u * stride;
        e[u] = idx >> 4;
        c[u] = idx & 15u;
    }
    #pragma unroll
    for (int u = 0; u < 4; u++) src[u] = __ldg(&ei0[e[u]]);
    #pragma unroll
    for (int u = 0; u < 4; u++) b[u] = __ldg(&batch[src[u]]);
    #pragma unroll
    for (int u = 0; u < 4; u++) s[u] = __ldg(&state[b[u]]);
    #pragma unroll
    for (int u = 0; u < 4; u++) {
        float4 v = __ldg(&se4[(unsigned)s[u] * 16u + c[u]]);
        __stcs(&out4[e[u] * 24u + 8u + c[u]], v);
    }
}

// ---------------- K2: logits, lane-per-node, broadcast weights ----------------
#define KC 16
__global__ __launch_bounds__(256) void k_logits(
    const float4* __restrict__ z4,    // z_atom as float4 [N*32]
    const float*  __restrict__ semb,  // [10,64]
    const float*  __restrict__ W1,    // [192,32]
    const float*  __restrict__ b1,    // [32]
    const float*  __restrict__ W2,    // [32]
    const float*  __restrict__ b2,    // [1]
    const int*    __restrict__ state, // [B]
    const int*    __restrict__ batch) // [N]
{
    __shared__ float ws[DEMB * 32];          // 16 KB, [k][j] row-major (matches W1)
    __shared__ float zs[8 * KC * 33];        // per-warp staging, [k][node], 16.9 KB
    __shared__ float sp_t[32 * 11];          // state part, [j][s] transposed
    __shared__ float w2s[32];

    int tid  = threadIdx.x;
    int lane = tid & 31;
    int wid  = tid >> 5;

    for (int t = tid; t < DEMB * 32; t += 256)
        ws[t] = __ldg(&W1[t]);
    for (int t = tid; t < 32 * 11; t += 256) {
        int j = t / 11, s = t - j * 11;
        float acc = 0.f;
        if (s < NSTATES) {
            acc = __ldg(&b1[j]);
            #pragma unroll 8
            for (int m = 0; m < DSTATE; m++)
                acc += __ldg(&semb[s * DSTATE + m]) * __ldg(&W1[(DEMB + m) * 32 + j]);
        }
        sp_t[t] = acc;
    }
    if (tid < 32) w2s[tid] = __ldg(&W2[tid]);
    __syncthreads();
    float b2v = __ldg(&b2[0]);

    unsigned n0 = (blockIdx.x * 8u + wid) * 32u;
    float* zsw = zs + wid * (KC * 33);

    int sidx = __ldg(&state[__ldg(&batch[n0 + lane])]);

    unsigned long long acc[16];
    #pragma unroll
    for (int q = 0; q < 16; q++) acc[q] = 0ull;

    int f  = lane & 3;
    int nd = lane >> 2;

    for (int cb = 0; cb < DEMB / 4 / 4; cb++) {   // 8 chunks of 16 k-values
        #pragma unroll
        for (int i = 0; i < 4; i++) {
            int node = nd + i * 8;
            float4 v = __ldg(&z4[(size_t)(n0 + node) * 32u + cb * 4 + f]);
            int kb = f * 4;
            zsw[(kb + 0) * 33 + node] = v.x;
            zsw[(kb + 1) * 33 + node] = v.y;
            zsw[(kb + 2) * 33 + node] = v.z;
            zsw[(kb + 3) * 33 + node] = v.w;
        }
        __syncwarp();

        #pragma unroll
        for (int k = 0; k < KC; k++) {
            float zv = zsw[k * 33 + lane];
            unsigned long long zvv = pk2(zv, zv);
            const ulonglong2* wr = (const ulonglong2*)(ws + (cb * KC + k) * 32);
            #pragma unroll
            for (int p = 0; p < 8; p++) {
                ulonglong2 wp = wr[p];      // broadcast LDS.128: 4 weights
                acc[2 * p]     = ffma2(zvv, wp.x, acc[2 * p]);
                acc[2 * p + 1] = ffma2(zvv, wp.y, acc[2 * p + 1]);
            }
        }
        __syncwarp();
    }

    float c = 0.f;
    #pragma unroll
    for (int q = 0; q < 16; q++) {
        float2 h2 = upk2(acc[q]);
        int j0 = 2 * q, j1 = 2 * q + 1;
        float h0 = h2.x + sp_t[j0 * 11 + sidx];
        float h1 = h2.y + sp_t[j1 * 11 + sidx];
        h0 = h0 > 0.f ? h0 : 0.01f * h0;
        h1 = h1 > 0.f ? h1 : 0.01f * h1;
        c += h0 * w2s[j0] + h1 * w2s[j1];
    }
    g_logits[n0 + lane] = c + b2v;
}

// ---------------- K3: segment softmax + weighted pool (float4 lanes) ----------
// Warp w handles nodes w, w+4, w+8,...; lane covers dims 4*lane..4*lane+3 via
// LDG.128 (coalesced 512B per warp per node). 2 independent acc chains.
__global__ __launch_bounds__(128) void k_pool(
    const float4* __restrict__ z4,    // z_atom as float4 [N*32]
    const float4* __restrict__ zm4,   // z_mol as float4 [B*32]
    float4*       __restrict__ out4)  // [B*64]
{
    int b = blockIdx.x;
    int tid = threadIdx.x;
    int lane = tid & 31, wid = tid >> 5;
    int lo = g_starts[b], hi = g_starts[b + 1];
    int cnt = hi - lo;

    __shared__ float  se[1024];
    __shared__ float  red[4];
    __shared__ float4 pacc[128];

    // segment max
    float m = -FLT_MAX;
    for (int i = tid; i < cnt; i += 128) m = fmaxf(m, g_logits[lo + i]);
    #pragma unroll
    for (int off = 16; off; off >>= 1) m = fmaxf(m, __shfl_xor_sync(0xffffffffu, m, off));
    if (lane == 0) red[wid] = m;
    __syncthreads();
    m = fmaxf(fmaxf(red[0], red[1]), fmaxf(red[2], red[3]));
    __syncthreads();

    // exp + segment sum (cache exp weights in smem)
    float s = 0.f;
    for (int i = tid; i < cnt; i += 128) {
        float e = __expf(g_logits[lo + i] - m);
        if (i < 1024) se[i] = e;
        s += e;
    }
    #pragma unroll
    for (int off = 16; off; off >>= 1) s += __shfl_xor_sync(0xffffffffu, s, off);
    if (lane == 0) red[wid] = s;
    __syncthreads();
    s = red[0] + red[1] + red[2] + red[3];
    float inv = 1.f / (s + 1e-16f);

    // weighted pool: warp per node (stride 4), lane = float4 dim group,
    // 2 independent chains (nodes i and i+4) for MLP.
    float4 a0 = make_float4(0.f, 0.f, 0.f, 0.f);
    float4 a1 = make_float4(0.f, 0.f, 0.f, 0.f);
    int i = wid;
    for (; i + 4 < cnt; i += 8) {
        float e0 = (i < 1024) ? se[i] : __expf(g_logits[lo + i] - m);
        float e1 = (i + 4 < 1024) ? se[i + 4] : __expf(g_logits[lo + i + 4] - m);
        float4 v0 = __ldg(&z4[(size_t)(lo + i) * 32 + lane]);
        float4 v1 = __ldg(&z4[(size_t)(lo + i + 4) * 32 + lane]);
        a0.x += e0 * v0.x; a0.y += e0 * v0.y; a0.z += e0 * v0.z; a0.w += e0 * v0.w;
        a1.x += e1 * v1.x; a1.y += e1 * v1.y; a1.z += e1 * v1.z; a1.w += e1 * v1.w;
    }
    for (; i < cnt; i += 4) {
        float e = (i < 1024) ? se[i] : __expf(g_logits[lo + i] - m);
        float4 v = __ldg(&z4[(size_t)(lo + i) * 32 + lane]);
        a0.x += e * v.x; a0.y += e * v.y; a0.z += e * v.z; a0.w += e * v.w;
    }
    a0.x += a1.x; a0.y += a1.y; a0.z += a1.z; a0.w += a1.w;
    pacc[wid * 32 + lane] = a0;
    __syncthreads();

    if (tid < 32) {
        float4 p0 = pacc[tid], p1 = pacc[32 + tid], p2 = pacc[64 + tid], p3 = pacc[96 + tid];
        float4 t;
        t.x = ((p0.x + p1.x) + (p2.x + p3.x)) * inv;
        t.y = ((p0.y + p1.y) + (p2.y + p3.y)) * inv;
        t.z = ((p0.z + p1.z) + (p2.z + p3.z)) * inv;
        t.w = ((p0.w + p1.w) + (p2.w + p3.w)) * inv;
        out4[(size_t)b * 64 + 32 + tid] = t;
    } else if (tid < 64) {
        int t = tid - 32;
        out4[(size_t)b * 64 + t] = __ldg(&zm4[(size_t)b * 32 + t]);
    }
}

// ---------------- launcher ----------------
// Launch order chosen so k_logits is the 4th launch (ncu -s 5 -c 1 captures it).
extern "C" void kernel_launch(void* const* d_in, const int* in_sizes, int n_in,
                              void* d_out, int out_size) {
    const float* edge_attr = (const float*)d_in[0];
    const float* z_mol     = (const float*)d_in[1];
    const float* z_atom    = (const float*)d_in[2];
    const float* state_emb = (const float*)d_in[3];
    const float* W1        = (const float*)d_in[4];
    const float* b1        = (const float*)d_in[5];
    const float* W2        = (const float*)d_in[6];
    const float* b2        = (const float*)d_in[7];
    const int*   state     = (const int*)d_in[8];
    const int*   ei0       = (const int*)d_in[9];
    const int*   batch     = (const int*)d_in[10];
    float* out = (float*)d_out;

    (void)in_sizes; (void)n_in; (void)out_size;

    k_starts<<<(NN + 255) / 256, 256>>>(batch);

    k_edge_copy<<<(NE * 4) / 256, 256>>>(
        (const float4*)edge_attr,
        (float4*)(out + (size_t)NB * 256));

    k_edge_state<<<(NE * 4) / 256, 256>>>(
        ei0, batch, state, (const float4*)state_emb,
        (float4*)(out + (size_t)NB * 256));

    k_logits<<<NN / 256, 256>>>(   // 4th launch -> profiled
        (const float4*)z_atom, state_emb, W1, b1, W2, b2, state, batch);

    k_pool<<<NB, 128>>>(
        (const float4*)z_atom, (const float4*)z_mol, (float4*)out);
}